// round 13
// baseline (speedup 1.0000x reference)
#include <cuda_runtime.h>
#include <cstdint>
#include <math.h>

#define BATCH 8
#define SEQ 1024
#define NDIM 768
#define HEADS 12
#define DHEAD 64
#define INNER 768
#define QKV_COLS 2304
#define ROWS_TOTAL (BATCH * SEQ)   // 8192

// ---------------------------------------------------------------------------
// Device scratch (no cudaMalloc allowed)
// ---------------------------------------------------------------------------
__device__ float g_qkv[ROWS_TOTAL * QKV_COLS];   // fp32 (tf32-rounded)
__device__ float g_xt[ROWS_TOTAL * NDIM];        // x, rounded, col-ilv
__device__ float g_wt[QKV_COLS * NDIM];          // w_qkv, rounded, col-ilv + K row-ilv
__device__ float g_att[ROWS_TOTAL * NDIM];       // attn out, rounded, col-ilv
__device__ float g_wot[NDIM * NDIM];             // w_out, rounded, col-ilv

// ---------------------------------------------------------------------------
// Helpers (baseline PTX, valid on compute_103)
// ---------------------------------------------------------------------------
__device__ __forceinline__ uint32_t smem_u32(const void* p) {
    uint32_t a;
    asm("{ .reg .u64 t; cvta.to.shared.u64 t, %1; cvt.u32.u64 %0, t; }"
        : "=r"(a) : "l"(p));
    return a;
}

__device__ __forceinline__ uint32_t f2tf32(float f) {
    uint32_t u;
    asm("cvt.rna.tf32.f32 %0, %1;" : "=r"(u) : "f"(f));
    return u;
}
__device__ __forceinline__ float rtf(float f) {
    return __uint_as_float(f2tf32(f));
}

__device__ __forceinline__ void mma_tf32(float* c, const uint32_t* a,
                                         uint32_t b0, uint32_t b1) {
    asm volatile(
        "mma.sync.aligned.m16n8k8.row.col.f32.tf32.tf32.f32 "
        "{%0,%1,%2,%3},{%4,%5,%6,%7},{%8,%9},{%0,%1,%2,%3};"
        : "+f"(c[0]), "+f"(c[1]), "+f"(c[2]), "+f"(c[3])
        : "r"(a[0]), "r"(a[1]), "r"(a[2]), "r"(a[3]), "r"(b0), "r"(b1));
}

__device__ __forceinline__ void cp_async16(uint32_t dst, const void* src) {
    asm volatile("cp.async.cg.shared.global [%0], [%1], 16;" ::"r"(dst),
                 "l"(src));
}
#define CP_COMMIT() asm volatile("cp.async.commit_group;" ::: "memory")
#define CP_WAIT0() asm volatile("cp.async.wait_group 0;" ::: "memory")
#define CP_WAIT1() asm volatile("cp.async.wait_group 1;" ::: "memory")

// k-col interleave placement (pairs (t4, t4+4) adjacent)
__device__ __forceinline__ int dplace(int j) {
    int b = j & 7;
    return (j & ~7) | (((b & 3) << 1) | (b >> 2));
}

// MUFU exp2 (hardware)
__device__ __forceinline__ float ex2_hw(float x) {
    float r;
    asm("ex2.approx.f32 %0, %1;" : "=f"(r) : "f"(x));
    return r;
}
// FMA-pipe exp2: degree-5 minimax 2^f on [0,1) + exponent bit injection.
// rel err ~2e-7 (far below tf32 operand noise).
__device__ __forceinline__ float ex2_fma(float x) {
    int ii = __float2int_rd(x);
    float f = x - (float)ii;
    float p = 1.8775767e-3f;
    p = fmaf(p, f, 8.9893397e-3f);
    p = fmaf(p, f, 5.5826318e-2f);
    p = fmaf(p, f, 2.4015361e-1f);
    p = fmaf(p, f, 6.9315308e-1f);
    p = fmaf(p, f, 1.0f);
    return __int_as_float(__float_as_int(p) + (ii << 23));
}

// ---------------------------------------------------------------------------
// Fused conversion kernel: fp32 -> tf32-rounded fp32, k-cols interleaved.
// ---------------------------------------------------------------------------
#define NG_X (ROWS_TOTAL * NDIM / 8)   // 786432
#define NG_W (QKV_COLS * NDIM / 8)     // 221184
#define NG_O (NDIM * NDIM / 8)         // 73728
#define NG_TOTAL (NG_X + NG_W + NG_O)

__global__ void __launch_bounds__(256) cvt_all(const float* __restrict__ x,
                                               const float* __restrict__ wq,
                                               const float* __restrict__ wo,
                                               float* __restrict__ xt,
                                               float* __restrict__ wt,
                                               float* __restrict__ wot) {
    const int GPR = NDIM / 8;  // 96 groups per row
    int i = blockIdx.x * blockDim.x + threadIdx.x;
    int stride = gridDim.x * blockDim.x;
    for (; i < NG_TOTAL; i += stride) {
        const float* src;
        float* dst;
        if (i < NG_X) {
            src = x + (size_t)i * 8;
            dst = xt + (size_t)i * 8;
        } else if (i < NG_X + NG_W) {
            int k = i - NG_X;
            int row = k / GPR;
            int gc = k - row * GPR;
            int drow = row;
            if (row >= INNER && row < 2 * INNER)
                drow = (row & ~63) | dplace(row & 63);
            src = wq + (size_t)k * 8;
            dst = wt + (size_t)drow * NDIM + gc * 8;
        } else {
            int k = i - NG_X - NG_W;
            src = wo + (size_t)k * 8;
            dst = wot + (size_t)k * 8;
        }
        float4 a = *(const float4*)src;
        float4 b = *(const float4*)(src + 4);
        float2* d = (float2*)dst;
        d[0] = make_float2(rtf(a.x), rtf(b.x));
        d[1] = make_float2(rtf(a.y), rtf(b.y));
        d[2] = make_float2(rtf(a.z), rtf(b.z));
        d[3] = make_float2(rtf(a.w), rtf(b.w));
    }
}

// ---------------------------------------------------------------------------
// tf32 single-pass GEMM via mma.sync (NT): C = A @ B^T (+bias)
// ---------------------------------------------------------------------------
#define FSTR 40
#define FTILE (128 * FSTR)
#define FBUF (2 * FTILE)
#define TGEMM_SMEM (2 * FBUF * 4)  // 81920 bytes

template <bool HAS_BIAS, bool ROUND_TF32>
__global__ void __launch_bounds__(256, 2) gemm_tf32(
    const float* __restrict__ A, const float* __restrict__ B,
    const float* __restrict__ bias, float* __restrict__ C, int M, int N,
    int K) {
    extern __shared__ uint32_t sm4[];
    const uint32_t sbase = smem_u32(sm4);

    const int tid = threadIdx.x;
    const int w = tid >> 5, l = tid & 31;
    const int g = l >> 2, t4 = l & 3;
    const int bm = blockIdx.y * 128, bn = blockIdx.x * 128;
    const int mrow0 = (w & 3) * 32, ncol0 = (w >> 2) * 64;

    float acc[2][8][4];
#pragma unroll
    for (int mi = 0; mi < 2; mi++)
#pragma unroll
        for (int ni = 0; ni < 8; ni++)
#pragma unroll
            for (int q = 0; q < 4; q++) acc[mi][ni][q] = 0.f;

    auto load_chunk = [&](int c) {
        const int k0 = c * 32;
        const uint32_t db = sbase + (uint32_t)(c & 1) * (FBUF * 4);
#pragma unroll
        for (int op = 0; op < 2; op++) {
            const float* src = op ? B : A;
            const int rb = op ? bn : bm;
#pragma unroll
            for (int i = 0; i < 4; i++) {
                int u = tid + i * 256;
                int row = u >> 3, seg = u & 7;
                cp_async16(db + (uint32_t)(op * FTILE + row * FSTR + seg * 4) * 4,
                           src + (size_t)(rb + row) * K + k0 + seg * 4);
            }
        }
        CP_COMMIT();
    };

    const int nchunk = K / 32;
    load_chunk(0);

    for (int c = 0; c < nchunk; c++) {
        CP_WAIT0();
        __syncthreads();
        if (c + 1 < nchunk) load_chunk(c + 1);

        const uint32_t ab = (uint32_t)(c & 1) * FBUF;
        const uint32_t bbw = ab + FTILE;

        auto loadf = [&](int k8, uint32_t af[2][4], uint2 bf[8]) {
            const int koff = k8 * 8 + 2 * t4;
#pragma unroll
            for (int mi = 0; mi < 2; mi++) {
                const int r0 = mrow0 + mi * 16 + g;
                uint2 u0 = *(const uint2*)&sm4[ab + r0 * FSTR + koff];
                uint2 u1 = *(const uint2*)&sm4[ab + (r0 + 8) * FSTR + koff];
                af[mi][0] = u0.x; af[mi][1] = u1.x;
                af[mi][2] = u0.y; af[mi][3] = u1.y;
            }
#pragma unroll
            for (int nt = 0; nt < 8; nt++)
                bf[nt] =
                    *(const uint2*)&sm4[bbw + (ncol0 + nt * 8 + g) * FSTR + koff];
        };
        auto mmaf = [&](uint32_t af[2][4], uint2 bf[8]) {
#pragma unroll
            for (int nt = 0; nt < 8; nt++) {
                mma_tf32(acc[0][nt], af[0], bf[nt].x, bf[nt].y);
                mma_tf32(acc[1][nt], af[1], bf[nt].x, bf[nt].y);
            }
        };

        uint32_t afA[2][4], afB[2][4];
        uint2 bfA[8], bfB[8];
        loadf(0, afA, bfA);
        loadf(1, afB, bfB);
        mmaf(afA, bfA);
        loadf(2, afA, bfA);
        mmaf(afB, bfB);
        loadf(3, afB, bfB);
        mmaf(afA, bfA);
        mmaf(afB, bfB);
    }

#pragma unroll
    for (int mi = 0; mi < 2; mi++) {
        const int r0 = bm + mrow0 + mi * 16 + g;
#pragma unroll
        for (int ni = 0; ni < 8; ni++) {
            const int col = bn + ncol0 + ni * 8 + 2 * t4;
            float b0v = 0.f, b1v = 0.f;
            if (HAS_BIAS) { b0v = bias[col]; b1v = bias[col + 1]; }
            float vals[4];
            vals[0] = acc[mi][ni][0] + b0v; vals[1] = acc[mi][ni][1] + b1v;
            vals[2] = acc[mi][ni][2] + b0v; vals[3] = acc[mi][ni][3] + b1v;
            if (ROUND_TF32) {
#pragma unroll
                for (int q = 0; q < 4; q++) vals[q] = rtf(vals[q]);
            }
            float2 v0, v1;
            v0.x = vals[0]; v0.y = vals[1];
            v1.x = vals[2]; v1.y = vals[3];
            *(float2*)(C + (size_t)r0 * N + col) = v0;
            *(float2*)(C + (size_t)(r0 + 8) * N + col) = v1;
        }
    }
}

// ---------------------------------------------------------------------------
// Fused shuffled-Q flash attention (tf32 mma.sync), no-rescale softmax,
// log2-domain scores (log2e folded into Q scale). 2^S computed half on the
// MUFU pipe (ex2.approx) and half on the fma/alu pipes (poly), balancing
// pipe load: MUFU was the binding pipe.
// ---------------------------------------------------------------------------
#define KSTR 72
#define VSTR 72
#define QSTR 72
#define KVBUF 9216                    // words: 64*72 + 64*72
#define VOFF 4608                     // words: 64*72
#define ATT_SMEM (2 * KVBUF * 4)      // 73728 bytes

__global__ void __launch_bounds__(256, 2) attn_kernel(
    const float* __restrict__ qkv, const int* __restrict__ perms,
    float* __restrict__ att_out) {
    extern __shared__ uint32_t sms[];
    const uint32_t sbase = smem_u32(sms);

    const int bh = blockIdx.y;
    const int b = bh / HEADS;
    const int h = bh % HEADS;
    const int q0 = blockIdx.x * 128;

    const int tid = threadIdx.x;
    const int w = tid >> 5, l = tid & 31;
    const int g = l >> 2, t4 = l & 3;
    const int qr0 = w * 16;

    const float* qkv_b = qkv + (size_t)b * SEQ * QKV_COLS;
    const int hoff = h * DHEAD;

    const int cp_row = tid >> 4;
    const int cp_seg = (tid & 15) * 4;

    auto issue_kv = [&](int t, int bsel) {
        const int kv0 = t * 64;
        const float* kb = qkv_b + (size_t)kv0 * QKV_COLS + hoff + INNER + cp_seg;
        const float* vb = kb + INNER;
        const uint32_t kd = sbase + (uint32_t)(bsel * KVBUF) * 4;
#pragma unroll
        for (int i = 0; i < 4; i++) {
            const int row = cp_row + i * 16;
            cp_async16(kd + (uint32_t)(row * KSTR + cp_seg) * 4,
                       kb + (size_t)row * QKV_COLS);
        }
#pragma unroll
        for (int i = 0; i < 4; i++) {
            const int row = cp_row + i * 16;
            cp_async16(kd + (uint32_t)(VOFF + row * VSTR + cp_seg) * 4,
                       vb + (size_t)row * QKV_COLS);
        }
        CP_COMMIT();
    };

    issue_kv(0, 0);

    // Stage Q (permuted gather, scale*log2e folded, tf32) d-interleaved.
    const float QSCALE = 0.125f * 1.44269504f;   // head-scale * log2(e)
    const int* ph = perms + (size_t)h * (SEQ * DHEAD) + q0 * DHEAD;
#pragma unroll 4
    for (int it = 0; it < 32; it++) {
        int f = it * 256 + tid;
        int p = ph[f];
        int nn = p >> 6, dd = p & 63;
        int i = f >> 6, j = f & 63;
        sms[KVBUF + i * QSTR + dplace(j)] =
            f2tf32(qkv_b[(size_t)nn * QKV_COLS + hoff + dd] * QSCALE);
    }
    __syncthreads();

    uint32_t qf[8][4];
#pragma unroll
    for (int kc = 0; kc < 8; kc++) {
        uint2 u0 = *(const uint2*)&sms[KVBUF + (qr0 + g) * QSTR + kc * 8 + 2 * t4];
        uint2 u1 =
            *(const uint2*)&sms[KVBUF + (qr0 + g + 8) * QSTR + kc * 8 + 2 * t4];
        qf[kc][0] = u0.x; qf[kc][2] = u0.y;
        qf[kc][1] = u1.x; qf[kc][3] = u1.y;
    }
    __syncthreads();   // buf1 free for tile 1

    float ls0 = 0.f, ls1 = 0.f;
    float O[8][4];
#pragma unroll
    for (int dt = 0; dt < 8; dt++)
#pragma unroll
        for (int q = 0; q < 4; q++) O[dt][q] = 0.f;

    const int srcA = (l & 28) | (t4 >> 1);
    const int srcB = srcA | 2;
    const bool lo_lane = (t4 & 1) != 0;

    for (int t = 0; t < 16; t++) {
        if (t < 15) {
            issue_kv(t + 1, (t + 1) & 1);
            CP_WAIT1();
        } else {
            CP_WAIT0();
        }
        __syncthreads();

        const uint32_t kw = (uint32_t)(t & 1) * KVBUF;
        const uint32_t vw = kw + VOFF;

        // S = Q @ K^T  (log2 domain)
        float S[8][4];
#pragma unroll
        for (int nt = 0; nt < 8; nt++)
#pragma unroll
            for (int q = 0; q < 4; q++) S[nt][q] = 0.f;
#pragma unroll
        for (int kc = 0; kc < 8; kc++) {
#pragma unroll
            for (int nt = 0; nt < 8; nt++) {
                uint2 kk = *(const uint2*)&sms[kw + (nt * 8 + g) * KSTR +
                                               kc * 8 + 2 * t4];
                mma_tf32(S[nt], qf[kc], kk.x, kk.y);
            }
        }

        // P = 2^S: half via MUFU ex2, half via fma-pipe poly (pipe balance).
#pragma unroll
        for (int nt = 0; nt < 8; nt++) {
            S[nt][0] = ex2_hw(S[nt][0]);
            S[nt][1] = ex2_fma(S[nt][1]);
            S[nt][2] = ex2_hw(S[nt][2]);
            S[nt][3] = ex2_fma(S[nt][3]);
            ls0 += S[nt][0] + S[nt][1];
            ls1 += S[nt][2] + S[nt][3];
        }

        // O += P @ V  (P fragments built via warp shuffles)
#pragma unroll
        for (int kc = 0; kc < 8; kc++) {
            uint32_t p0 = f2tf32(S[kc][0]);
            uint32_t p1 = f2tf32(S[kc][1]);
            uint32_t p2 = f2tf32(S[kc][2]);
            uint32_t p3 = f2tf32(S[kc][3]);
            uint32_t v00 = __shfl_sync(0xffffffffu, p0, srcA);
            uint32_t v01 = __shfl_sync(0xffffffffu, p1, srcA);
            uint32_t v10 = __shfl_sync(0xffffffffu, p2, srcA);
            uint32_t v11 = __shfl_sync(0xffffffffu, p3, srcA);
            uint32_t w00 = __shfl_sync(0xffffffffu, p0, srcB);
            uint32_t w01 = __shfl_sync(0xffffffffu, p1, srcB);
            uint32_t w10 = __shfl_sync(0xffffffffu, p2, srcB);
            uint32_t w11 = __shfl_sync(0xffffffffu, p3, srcB);
            uint32_t a[4];
            a[0] = lo_lane ? v01 : v00;
            a[1] = lo_lane ? v11 : v10;
            a[2] = lo_lane ? w01 : w00;
            a[3] = lo_lane ? w11 : w10;
#pragma unroll
            for (int dt = 0; dt < 8; dt++) {
                uint32_t b0 = sms[vw + (kc * 8 + t4) * VSTR + dt * 8 + g];
                uint32_t b1 = sms[vw + (kc * 8 + t4 + 4) * VSTR + dt * 8 + g];
                mma_tf32(O[dt], a, b0, b1);
            }
        }
        __syncthreads();
    }

    // Final row-sum reduction across the 4 t4 lanes of each row.
    ls0 += __shfl_xor_sync(0xffffffffu, ls0, 1);
    ls0 += __shfl_xor_sync(0xffffffffu, ls0, 2);
    ls1 += __shfl_xor_sync(0xffffffffu, ls1, 1);
    ls1 += __shfl_xor_sync(0xffffffffu, ls1, 2);

    // Epilogue: normalize, tf32-round, write fp32 att with interleaved cols.
    const float inv0 = 1.0f / ls0;
    const float inv1 = 1.0f / ls1;
    const size_t r0off = ((size_t)b * SEQ + q0 + qr0 + g) * NDIM + hoff;
    const size_t r1off = r0off + (size_t)8 * NDIM;
    const int p0c = dplace(2 * t4);
    const int p1c = dplace(2 * t4 + 1);
#pragma unroll
    for (int dt = 0; dt < 8; dt++) {
        att_out[r0off + dt * 8 + p0c] = rtf(O[dt][0] * inv0);
        att_out[r0off + dt * 8 + p1c] = rtf(O[dt][1] * inv0);
        att_out[r1off + dt * 8 + p0c] = rtf(O[dt][2] * inv1);
        att_out[r1off + dt * 8 + p1c] = rtf(O[dt][3] * inv1);
    }
}

// ---------------------------------------------------------------------------
extern "C" void kernel_launch(void* const* d_in, const int* in_sizes, int n_in,
                              void* d_out, int out_size) {
    const float* x     = (const float*)d_in[0];
    const float* w_qkv = (const float*)d_in[1];
    const float* w_out = (const float*)d_in[2];
    const float* b_out = (const float*)d_in[3];
    const int*   perms = (const int*)d_in[4];
    float* out = (float*)d_out;

    float *qkv, *xt, *wt, *att, *wot;
    cudaGetSymbolAddress((void**)&qkv, g_qkv);
    cudaGetSymbolAddress((void**)&xt, g_xt);
    cudaGetSymbolAddress((void**)&wt, g_wt);
    cudaGetSymbolAddress((void**)&att, g_att);
    cudaGetSymbolAddress((void**)&wot, g_wot);

    cudaFuncSetAttribute(attn_kernel, cudaFuncAttributeMaxDynamicSharedMemorySize,
                         ATT_SMEM);
    cudaFuncSetAttribute((const void*)gemm_tf32<false, true>,
                         cudaFuncAttributeMaxDynamicSharedMemorySize, TGEMM_SMEM);
    cudaFuncSetAttribute((const void*)gemm_tf32<true, false>,
                         cudaFuncAttributeMaxDynamicSharedMemorySize, TGEMM_SMEM);

    // 1) one fused conversion launch: x, w_qkv (K-row ilv), w_out
    cvt_all<<<2048, 256>>>(x, w_qkv, w_out, xt, wt, wot);

    // 2) qkv = x @ w_qkv^T
    {
        dim3 grid(QKV_COLS / 128, ROWS_TOTAL / 128);  // (18, 64)
        gemm_tf32<false, true><<<grid, 256, TGEMM_SMEM>>>(
            xt, wt, nullptr, qkv, ROWS_TOTAL, QKV_COLS, NDIM);
    }
    // 3) fused shuffled-Q attention -> att (fp32, col-ilv)
    {
        dim3 grid(SEQ / 128, BATCH * HEADS);  // (8, 96)
        attn_kernel<<<grid, 256, ATT_SMEM>>>(qkv, perms, att);
    }
    // 4) out = att @ w_out^T + b_out
    {
        dim3 grid(NDIM / 128, ROWS_TOTAL / 128);  // (6, 64)
        gemm_tf32<true, false><<<grid, 256, TGEMM_SMEM>>>(
            att, wot, b_out, out, ROWS_TOTAL, NDIM, NDIM);
    }
}

// round 14
// speedup vs baseline: 1.0230x; 1.0230x over previous
#include <cuda_runtime.h>
#include <cstdint>
#include <math.h>

#define BATCH 8
#define SEQ 1024
#define NDIM 768
#define HEADS 12
#define DHEAD 64
#define INNER 768
#define QKV_COLS 2304
#define ROWS_TOTAL (BATCH * SEQ)   // 8192

// ---------------------------------------------------------------------------
// Device scratch (no cudaMalloc allowed)
// ---------------------------------------------------------------------------
__device__ float g_qkv[ROWS_TOTAL * QKV_COLS];   // fp32 (tf32-rounded)
__device__ float g_xt[ROWS_TOTAL * NDIM];        // x, rounded, col-ilv
__device__ float g_wt[QKV_COLS * NDIM];          // w_qkv, rounded, col-ilv + K row-ilv
__device__ float g_att[ROWS_TOTAL * NDIM];       // attn out, rounded, col-ilv
__device__ float g_wot[NDIM * NDIM];             // w_out, rounded, col-ilv

// ---------------------------------------------------------------------------
// Helpers (baseline PTX, valid on compute_103)
// ---------------------------------------------------------------------------
__device__ __forceinline__ uint32_t smem_u32(const void* p) {
    uint32_t a;
    asm("{ .reg .u64 t; cvta.to.shared.u64 t, %1; cvt.u32.u64 %0, t; }"
        : "=r"(a) : "l"(p));
    return a;
}

__device__ __forceinline__ uint32_t f2tf32(float f) {
    uint32_t u;
    asm("cvt.rna.tf32.f32 %0, %1;" : "=r"(u) : "f"(f));
    return u;
}
__device__ __forceinline__ float rtf(float f) {
    return __uint_as_float(f2tf32(f));
}

__device__ __forceinline__ void mma_tf32(float* c, const uint32_t* a,
                                         uint32_t b0, uint32_t b1) {
    asm volatile(
        "mma.sync.aligned.m16n8k8.row.col.f32.tf32.tf32.f32 "
        "{%0,%1,%2,%3},{%4,%5,%6,%7},{%8,%9},{%0,%1,%2,%3};"
        : "+f"(c[0]), "+f"(c[1]), "+f"(c[2]), "+f"(c[3])
        : "r"(a[0]), "r"(a[1]), "r"(a[2]), "r"(a[3]), "r"(b0), "r"(b1));
}

__device__ __forceinline__ void cp_async16(uint32_t dst, const void* src) {
    asm volatile("cp.async.cg.shared.global [%0], [%1], 16;" ::"r"(dst),
                 "l"(src));
}
#define CP_COMMIT() asm volatile("cp.async.commit_group;" ::: "memory")
#define CP_WAIT0() asm volatile("cp.async.wait_group 0;" ::: "memory")
#define CP_WAIT1() asm volatile("cp.async.wait_group 1;" ::: "memory")

// k-col interleave placement (pairs (t4, t4+4) adjacent)
__device__ __forceinline__ int dplace(int j) {
    int b = j & 7;
    return (j & ~7) | (((b & 3) << 1) | (b >> 2));
}

// MUFU exp2 (hardware)
__device__ __forceinline__ float ex2_hw(float x) {
    float r;
    asm("ex2.approx.f32 %0, %1;" : "=f"(r) : "f"(x));
    return r;
}

// ---------------------------------------------------------------------------
// Fused conversion kernel: fp32 -> tf32-rounded fp32, k-cols interleaved.
// ---------------------------------------------------------------------------
#define NG_X (ROWS_TOTAL * NDIM / 8)   // 786432
#define NG_W (QKV_COLS * NDIM / 8)     // 221184
#define NG_O (NDIM * NDIM / 8)         // 73728
#define NG_TOTAL (NG_X + NG_W + NG_O)

__global__ void __launch_bounds__(256) cvt_all(const float* __restrict__ x,
                                               const float* __restrict__ wq,
                                               const float* __restrict__ wo,
                                               float* __restrict__ xt,
                                               float* __restrict__ wt,
                                               float* __restrict__ wot) {
    const int GPR = NDIM / 8;  // 96 groups per row
    int i = blockIdx.x * blockDim.x + threadIdx.x;
    int stride = gridDim.x * blockDim.x;
    for (; i < NG_TOTAL; i += stride) {
        const float* src;
        float* dst;
        if (i < NG_X) {
            src = x + (size_t)i * 8;
            dst = xt + (size_t)i * 8;
        } else if (i < NG_X + NG_W) {
            int k = i - NG_X;
            int row = k / GPR;
            int gc = k - row * GPR;
            int drow = row;
            if (row >= INNER && row < 2 * INNER)
                drow = (row & ~63) | dplace(row & 63);
            src = wq + (size_t)k * 8;
            dst = wt + (size_t)drow * NDIM + gc * 8;
        } else {
            int k = i - NG_X - NG_W;
            src = wo + (size_t)k * 8;
            dst = wot + (size_t)k * 8;
        }
        float4 a = *(const float4*)src;
        float4 b = *(const float4*)(src + 4);
        float2* d = (float2*)dst;
        d[0] = make_float2(rtf(a.x), rtf(b.x));
        d[1] = make_float2(rtf(a.y), rtf(b.y));
        d[2] = make_float2(rtf(a.z), rtf(b.z));
        d[3] = make_float2(rtf(a.w), rtf(b.w));
    }
}

// ---------------------------------------------------------------------------
// tf32 single-pass GEMM via mma.sync (NT): C = A @ B^T (+bias)
// ---------------------------------------------------------------------------
#define FSTR 40
#define FTILE (128 * FSTR)
#define FBUF (2 * FTILE)
#define TGEMM_SMEM (2 * FBUF * 4)  // 81920 bytes

template <bool HAS_BIAS, bool ROUND_TF32>
__global__ void __launch_bounds__(256, 2) gemm_tf32(
    const float* __restrict__ A, const float* __restrict__ B,
    const float* __restrict__ bias, float* __restrict__ C, int M, int N,
    int K) {
    extern __shared__ uint32_t sm4[];
    const uint32_t sbase = smem_u32(sm4);

    const int tid = threadIdx.x;
    const int w = tid >> 5, l = tid & 31;
    const int g = l >> 2, t4 = l & 3;
    const int bm = blockIdx.y * 128, bn = blockIdx.x * 128;
    const int mrow0 = (w & 3) * 32, ncol0 = (w >> 2) * 64;

    float acc[2][8][4];
#pragma unroll
    for (int mi = 0; mi < 2; mi++)
#pragma unroll
        for (int ni = 0; ni < 8; ni++)
#pragma unroll
            for (int q = 0; q < 4; q++) acc[mi][ni][q] = 0.f;

    auto load_chunk = [&](int c) {
        const int k0 = c * 32;
        const uint32_t db = sbase + (uint32_t)(c & 1) * (FBUF * 4);
#pragma unroll
        for (int op = 0; op < 2; op++) {
            const float* src = op ? B : A;
            const int rb = op ? bn : bm;
#pragma unroll
            for (int i = 0; i < 4; i++) {
                int u = tid + i * 256;
                int row = u >> 3, seg = u & 7;
                cp_async16(db + (uint32_t)(op * FTILE + row * FSTR + seg * 4) * 4,
                           src + (size_t)(rb + row) * K + k0 + seg * 4);
            }
        }
        CP_COMMIT();
    };

    const int nchunk = K / 32;
    load_chunk(0);

    for (int c = 0; c < nchunk; c++) {
        CP_WAIT0();
        __syncthreads();
        if (c + 1 < nchunk) load_chunk(c + 1);

        const uint32_t ab = (uint32_t)(c & 1) * FBUF;
        const uint32_t bbw = ab + FTILE;

        auto loadf = [&](int k8, uint32_t af[2][4], uint2 bf[8]) {
            const int koff = k8 * 8 + 2 * t4;
#pragma unroll
            for (int mi = 0; mi < 2; mi++) {
                const int r0 = mrow0 + mi * 16 + g;
                uint2 u0 = *(const uint2*)&sm4[ab + r0 * FSTR + koff];
                uint2 u1 = *(const uint2*)&sm4[ab + (r0 + 8) * FSTR + koff];
                af[mi][0] = u0.x; af[mi][1] = u1.x;
                af[mi][2] = u0.y; af[mi][3] = u1.y;
            }
#pragma unroll
            for (int nt = 0; nt < 8; nt++)
                bf[nt] =
                    *(const uint2*)&sm4[bbw + (ncol0 + nt * 8 + g) * FSTR + koff];
        };
        auto mmaf = [&](uint32_t af[2][4], uint2 bf[8]) {
#pragma unroll
            for (int nt = 0; nt < 8; nt++) {
                mma_tf32(acc[0][nt], af[0], bf[nt].x, bf[nt].y);
                mma_tf32(acc[1][nt], af[1], bf[nt].x, bf[nt].y);
            }
        };

        uint32_t afA[2][4], afB[2][4];
        uint2 bfA[8], bfB[8];
        loadf(0, afA, bfA);
        loadf(1, afB, bfB);
        mmaf(afA, bfA);
        loadf(2, afA, bfA);
        mmaf(afB, bfB);
        loadf(3, afB, bfB);
        mmaf(afA, bfA);
        mmaf(afB, bfB);
    }

#pragma unroll
    for (int mi = 0; mi < 2; mi++) {
        const int r0 = bm + mrow0 + mi * 16 + g;
#pragma unroll
        for (int ni = 0; ni < 8; ni++) {
            const int col = bn + ncol0 + ni * 8 + 2 * t4;
            float b0v = 0.f, b1v = 0.f;
            if (HAS_BIAS) { b0v = bias[col]; b1v = bias[col + 1]; }
            float vals[4];
            vals[0] = acc[mi][ni][0] + b0v; vals[1] = acc[mi][ni][1] + b1v;
            vals[2] = acc[mi][ni][2] + b0v; vals[3] = acc[mi][ni][3] + b1v;
            if (ROUND_TF32) {
#pragma unroll
                for (int q = 0; q < 4; q++) vals[q] = rtf(vals[q]);
            }
            float2 v0, v1;
            v0.x = vals[0]; v0.y = vals[1];
            v1.x = vals[2]; v1.y = vals[3];
            *(float2*)(C + (size_t)r0 * N + col) = v0;
            *(float2*)(C + (size_t)(r0 + 8) * N + col) = v1;
        }
    }
}

// ---------------------------------------------------------------------------
// Fused shuffled-Q flash attention (tf32 mma.sync), no-rescale softmax,
// log2-domain scores (log2e folded into Q scale), all-MUFU ex2 (R12 structure
// — the poly split of R13 burned more issue slots than it saved).
// ---------------------------------------------------------------------------
#define KSTR 72
#define VSTR 72
#define QSTR 72
#define KVBUF 9216                    // words: 64*72 + 64*72
#define VOFF 4608                     // words: 64*72
#define ATT_SMEM (2 * KVBUF * 4)      // 73728 bytes

__global__ void __launch_bounds__(256, 2) attn_kernel(
    const float* __restrict__ qkv, const int* __restrict__ perms,
    float* __restrict__ att_out) {
    extern __shared__ uint32_t sms[];
    const uint32_t sbase = smem_u32(sms);

    const int bh = blockIdx.y;
    const int b = bh / HEADS;
    const int h = bh % HEADS;
    const int q0 = blockIdx.x * 128;

    const int tid = threadIdx.x;
    const int w = tid >> 5, l = tid & 31;
    const int g = l >> 2, t4 = l & 3;
    const int qr0 = w * 16;

    const float* qkv_b = qkv + (size_t)b * SEQ * QKV_COLS;
    const int hoff = h * DHEAD;

    const int cp_row = tid >> 4;
    const int cp_seg = (tid & 15) * 4;

    auto issue_kv = [&](int t, int bsel) {
        const int kv0 = t * 64;
        const float* kb = qkv_b + (size_t)kv0 * QKV_COLS + hoff + INNER + cp_seg;
        const float* vb = kb + INNER;
        const uint32_t kd = sbase + (uint32_t)(bsel * KVBUF) * 4;
#pragma unroll
        for (int i = 0; i < 4; i++) {
            const int row = cp_row + i * 16;
            cp_async16(kd + (uint32_t)(row * KSTR + cp_seg) * 4,
                       kb + (size_t)row * QKV_COLS);
        }
#pragma unroll
        for (int i = 0; i < 4; i++) {
            const int row = cp_row + i * 16;
            cp_async16(kd + (uint32_t)(VOFF + row * VSTR + cp_seg) * 4,
                       vb + (size_t)row * QKV_COLS);
        }
        CP_COMMIT();
    };

    issue_kv(0, 0);

    // Stage Q (permuted gather, scale*log2e folded, tf32) d-interleaved.
    const float QSCALE = 0.125f * 1.44269504f;   // head-scale * log2(e)
    const int* ph = perms + (size_t)h * (SEQ * DHEAD) + q0 * DHEAD;
#pragma unroll 4
    for (int it = 0; it < 32; it++) {
        int f = it * 256 + tid;
        int p = ph[f];
        int nn = p >> 6, dd = p & 63;
        int i = f >> 6, j = f & 63;
        sms[KVBUF + i * QSTR + dplace(j)] =
            f2tf32(qkv_b[(size_t)nn * QKV_COLS + hoff + dd] * QSCALE);
    }
    __syncthreads();

    uint32_t qf[8][4];
#pragma unroll
    for (int kc = 0; kc < 8; kc++) {
        uint2 u0 = *(const uint2*)&sms[KVBUF + (qr0 + g) * QSTR + kc * 8 + 2 * t4];
        uint2 u1 =
            *(const uint2*)&sms[KVBUF + (qr0 + g + 8) * QSTR + kc * 8 + 2 * t4];
        qf[kc][0] = u0.x; qf[kc][2] = u0.y;
        qf[kc][1] = u1.x; qf[kc][3] = u1.y;
    }
    __syncthreads();   // buf1 free for tile 1

    float ls0 = 0.f, ls1 = 0.f;
    float O[8][4];
#pragma unroll
    for (int dt = 0; dt < 8; dt++)
#pragma unroll
        for (int q = 0; q < 4; q++) O[dt][q] = 0.f;

    const int srcA = (l & 28) | (t4 >> 1);
    const int srcB = srcA | 2;
    const bool lo_lane = (t4 & 1) != 0;

    for (int t = 0; t < 16; t++) {
        if (t < 15) {
            issue_kv(t + 1, (t + 1) & 1);
            CP_WAIT1();
        } else {
            CP_WAIT0();
        }
        __syncthreads();

        const uint32_t kw = (uint32_t)(t & 1) * KVBUF;
        const uint32_t vw = kw + VOFF;

        // S = Q @ K^T  (log2 domain)
        float S[8][4];
#pragma unroll
        for (int nt = 0; nt < 8; nt++)
#pragma unroll
            for (int q = 0; q < 4; q++) S[nt][q] = 0.f;
#pragma unroll
        for (int kc = 0; kc < 8; kc++) {
#pragma unroll
            for (int nt = 0; nt < 8; nt++) {
                uint2 kk = *(const uint2*)&sms[kw + (nt * 8 + g) * KSTR +
                                               kc * 8 + 2 * t4];
                mma_tf32(S[nt], qf[kc], kk.x, kk.y);
            }
        }

        // P = 2^S (single MUFU op per element); per-thread partial sums.
#pragma unroll
        for (int nt = 0; nt < 8; nt++) {
            S[nt][0] = ex2_hw(S[nt][0]);
            S[nt][1] = ex2_hw(S[nt][1]);
            S[nt][2] = ex2_hw(S[nt][2]);
            S[nt][3] = ex2_hw(S[nt][3]);
            ls0 += S[nt][0] + S[nt][1];
            ls1 += S[nt][2] + S[nt][3];
        }

        // O += P @ V  (P fragments built via warp shuffles)
#pragma unroll
        for (int kc = 0; kc < 8; kc++) {
            uint32_t p0 = f2tf32(S[kc][0]);
            uint32_t p1 = f2tf32(S[kc][1]);
            uint32_t p2 = f2tf32(S[kc][2]);
            uint32_t p3 = f2tf32(S[kc][3]);
            uint32_t v00 = __shfl_sync(0xffffffffu, p0, srcA);
            uint32_t v01 = __shfl_sync(0xffffffffu, p1, srcA);
            uint32_t v10 = __shfl_sync(0xffffffffu, p2, srcA);
            uint32_t v11 = __shfl_sync(0xffffffffu, p3, srcA);
            uint32_t w00 = __shfl_sync(0xffffffffu, p0, srcB);
            uint32_t w01 = __shfl_sync(0xffffffffu, p1, srcB);
            uint32_t w10 = __shfl_sync(0xffffffffu, p2, srcB);
            uint32_t w11 = __shfl_sync(0xffffffffu, p3, srcB);
            uint32_t a[4];
            a[0] = lo_lane ? v01 : v00;
            a[1] = lo_lane ? v11 : v10;
            a[2] = lo_lane ? w01 : w00;
            a[3] = lo_lane ? w11 : w10;
#pragma unroll
            for (int dt = 0; dt < 8; dt++) {
                uint32_t b0 = sms[vw + (kc * 8 + t4) * VSTR + dt * 8 + g];
                uint32_t b1 = sms[vw + (kc * 8 + t4 + 4) * VSTR + dt * 8 + g];
                mma_tf32(O[dt], a, b0, b1);
            }
        }
        __syncthreads();
    }

    // Final row-sum reduction across the 4 t4 lanes of each row.
    ls0 += __shfl_xor_sync(0xffffffffu, ls0, 1);
    ls0 += __shfl_xor_sync(0xffffffffu, ls0, 2);
    ls1 += __shfl_xor_sync(0xffffffffu, ls1, 1);
    ls1 += __shfl_xor_sync(0xffffffffu, ls1, 2);

    // Epilogue: normalize, tf32-round, write fp32 att with interleaved cols.
    const float inv0 = 1.0f / ls0;
    const float inv1 = 1.0f / ls1;
    const size_t r0off = ((size_t)b * SEQ + q0 + qr0 + g) * NDIM + hoff;
    const size_t r1off = r0off + (size_t)8 * NDIM;
    const int p0c = dplace(2 * t4);
    const int p1c = dplace(2 * t4 + 1);
#pragma unroll
    for (int dt = 0; dt < 8; dt++) {
        att_out[r0off + dt * 8 + p0c] = rtf(O[dt][0] * inv0);
        att_out[r0off + dt * 8 + p1c] = rtf(O[dt][1] * inv0);
        att_out[r1off + dt * 8 + p0c] = rtf(O[dt][2] * inv1);
        att_out[r1off + dt * 8 + p1c] = rtf(O[dt][3] * inv1);
    }
}

// ---------------------------------------------------------------------------
extern "C" void kernel_launch(void* const* d_in, const int* in_sizes, int n_in,
                              void* d_out, int out_size) {
    const float* x     = (const float*)d_in[0];
    const float* w_qkv = (const float*)d_in[1];
    const float* w_out = (const float*)d_in[2];
    const float* b_out = (const float*)d_in[3];
    const int*   perms = (const int*)d_in[4];
    float* out = (float*)d_out;

    float *qkv, *xt, *wt, *att, *wot;
    cudaGetSymbolAddress((void**)&qkv, g_qkv);
    cudaGetSymbolAddress((void**)&xt, g_xt);
    cudaGetSymbolAddress((void**)&wt, g_wt);
    cudaGetSymbolAddress((void**)&att, g_att);
    cudaGetSymbolAddress((void**)&wot, g_wot);

    cudaFuncSetAttribute(attn_kernel, cudaFuncAttributeMaxDynamicSharedMemorySize,
                         ATT_SMEM);
    cudaFuncSetAttribute((const void*)gemm_tf32<false, true>,
                         cudaFuncAttributeMaxDynamicSharedMemorySize, TGEMM_SMEM);
    cudaFuncSetAttribute((const void*)gemm_tf32<true, false>,
                         cudaFuncAttributeMaxDynamicSharedMemorySize, TGEMM_SMEM);

    // 1) one fused conversion launch: x, w_qkv (K-row ilv), w_out
    cvt_all<<<2048, 256>>>(x, w_qkv, w_out, xt, wt, wot);

    // 2) qkv = x @ w_qkv^T
    {
        dim3 grid(QKV_COLS / 128, ROWS_TOTAL / 128);  // (18, 64)
        gemm_tf32<false, true><<<grid, 256, TGEMM_SMEM>>>(
            xt, wt, nullptr, qkv, ROWS_TOTAL, QKV_COLS, NDIM);
    }
    // 3) fused shuffled-Q attention -> att (fp32, col-ilv)
    {
        dim3 grid(SEQ / 128, BATCH * HEADS);  // (8, 96)
        attn_kernel<<<grid, 256, ATT_SMEM>>>(qkv, perms, att);
    }
    // 4) out = att @ w_out^T + b_out
    {
        dim3 grid(NDIM / 128, ROWS_TOTAL / 128);  // (6, 64)
        gemm_tf32<true, false><<<grid, 256, TGEMM_SMEM>>>(
            att, wot, b_out, out, ROWS_TOTAL, NDIM, NDIM);
    }
}

// round 15
// speedup vs baseline: 1.0263x; 1.0032x over previous
#include <cuda_runtime.h>
#include <cstdint>
#include <math.h>

#define BATCH 8
#define SEQ 1024
#define NDIM 768
#define HEADS 12
#define DHEAD 64
#define INNER 768
#define QKV_COLS 2304
#define ROWS_TOTAL (BATCH * SEQ)   // 8192

// ---------------------------------------------------------------------------
// Device scratch (no cudaMalloc allowed)
// ---------------------------------------------------------------------------
__device__ float g_qkv[ROWS_TOTAL * QKV_COLS];   // fp32 (tf32-rounded)
__device__ float g_xt[ROWS_TOTAL * NDIM];        // x, rounded, col-ilv
__device__ float g_wt[QKV_COLS * NDIM];          // w_qkv, rounded, col-ilv + K row-ilv
__device__ float g_att[ROWS_TOTAL * NDIM];       // attn out, rounded, col-ilv
__device__ float g_wot[NDIM * NDIM];             // w_out, rounded, col-ilv

// ---------------------------------------------------------------------------
// Helpers (baseline PTX, valid on compute_103)
// ---------------------------------------------------------------------------
__device__ __forceinline__ uint32_t smem_u32(const void* p) {
    uint32_t a;
    asm("{ .reg .u64 t; cvta.to.shared.u64 t, %1; cvt.u32.u64 %0, t; }"
        : "=r"(a) : "l"(p));
    return a;
}

__device__ __forceinline__ uint32_t f2tf32(float f) {
    uint32_t u;
    asm("cvt.rna.tf32.f32 %0, %1;" : "=r"(u) : "f"(f));
    return u;
}
__device__ __forceinline__ float rtf(float f) {
    return __uint_as_float(f2tf32(f));
}

__device__ __forceinline__ void mma_tf32(float* c, const uint32_t* a,
                                         uint32_t b0, uint32_t b1) {
    asm volatile(
        "mma.sync.aligned.m16n8k8.row.col.f32.tf32.tf32.f32 "
        "{%0,%1,%2,%3},{%4,%5,%6,%7},{%8,%9},{%0,%1,%2,%3};"
        : "+f"(c[0]), "+f"(c[1]), "+f"(c[2]), "+f"(c[3])
        : "r"(a[0]), "r"(a[1]), "r"(a[2]), "r"(a[3]), "r"(b0), "r"(b1));
}

__device__ __forceinline__ void cp_async16(uint32_t dst, const void* src) {
    asm volatile("cp.async.cg.shared.global [%0], [%1], 16;" ::"r"(dst),
                 "l"(src));
}
#define CP_COMMIT() asm volatile("cp.async.commit_group;" ::: "memory")
#define CP_WAIT0() asm volatile("cp.async.wait_group 0;" ::: "memory")
#define CP_WAIT1() asm volatile("cp.async.wait_group 1;" ::: "memory")

// k-col interleave placement (pairs (t4, t4+4) adjacent)
__device__ __forceinline__ int dplace(int j) {
    int b = j & 7;
    return (j & ~7) | (((b & 3) << 1) | (b >> 2));
}

// MUFU exp2 (hardware)
__device__ __forceinline__ float ex2_hw(float x) {
    float r;
    asm("ex2.approx.f32 %0, %1;" : "=f"(r) : "f"(x));
    return r;
}

// ---------------------------------------------------------------------------
// Fused conversion kernel: fp32 -> tf32-rounded fp32, k-cols interleaved.
// ---------------------------------------------------------------------------
#define NG_X (ROWS_TOTAL * NDIM / 8)   // 786432
#define NG_W (QKV_COLS * NDIM / 8)     // 221184
#define NG_O (NDIM * NDIM / 8)         // 73728
#define NG_TOTAL (NG_X + NG_W + NG_O)

__global__ void __launch_bounds__(256) cvt_all(const float* __restrict__ x,
                                               const float* __restrict__ wq,
                                               const float* __restrict__ wo,
                                               float* __restrict__ xt,
                                               float* __restrict__ wt,
                                               float* __restrict__ wot) {
    const int GPR = NDIM / 8;  // 96 groups per row
    int i = blockIdx.x * blockDim.x + threadIdx.x;
    int stride = gridDim.x * blockDim.x;
    for (; i < NG_TOTAL; i += stride) {
        const float* src;
        float* dst;
        if (i < NG_X) {
            src = x + (size_t)i * 8;
            dst = xt + (size_t)i * 8;
        } else if (i < NG_X + NG_W) {
            int k = i - NG_X;
            int row = k / GPR;
            int gc = k - row * GPR;
            int drow = row;
            if (row >= INNER && row < 2 * INNER)
                drow = (row & ~63) | dplace(row & 63);
            src = wq + (size_t)k * 8;
            dst = wt + (size_t)drow * NDIM + gc * 8;
        } else {
            int k = i - NG_X - NG_W;
            src = wo + (size_t)k * 8;
            dst = wot + (size_t)k * 8;
        }
        float4 a = *(const float4*)src;
        float4 b = *(const float4*)(src + 4);
        float2* d = (float2*)dst;
        d[0] = make_float2(rtf(a.x), rtf(b.x));
        d[1] = make_float2(rtf(a.y), rtf(b.y));
        d[2] = make_float2(rtf(a.z), rtf(b.z));
        d[3] = make_float2(rtf(a.w), rtf(b.w));
    }
}

// ---------------------------------------------------------------------------
// tf32 single-pass GEMM via mma.sync (NT): C = A @ B^T (+bias)
// Templated BM/BN/THREADS/MAXB. Warp tile 32x64. BK=32, dbl-buffered smem,
// fragment double-buffering across k8 steps.
// ---------------------------------------------------------------------------
#define FSTR 40

template <int BM, int BN, int THREADS, int MAXB, bool HAS_BIAS, bool ROUND_TF32>
__global__ void __launch_bounds__(THREADS, MAXB) gemm_tf32(
    const float* __restrict__ A, const float* __restrict__ B,
    const float* __restrict__ bias, float* __restrict__ C, int M, int N,
    int K) {
    constexpr int WMC = BM / 32;                 // M-warps
    constexpr int FTILEA = BM * FSTR;
    constexpr int FBUFW = (BM + BN) * FSTR;
    extern __shared__ uint32_t sm4[];
    const uint32_t sbase = smem_u32(sm4);

    const int tid = threadIdx.x;
    const int w = tid >> 5, l = tid & 31;
    const int g = l >> 2, t4 = l & 3;
    const int bm = blockIdx.y * BM, bn = blockIdx.x * BN;
    const int mrow0 = (w % WMC) * 32, ncol0 = (w / WMC) * 64;

    float acc[2][8][4];
#pragma unroll
    for (int mi = 0; mi < 2; mi++)
#pragma unroll
        for (int ni = 0; ni < 8; ni++)
#pragma unroll
            for (int q = 0; q < 4; q++) acc[mi][ni][q] = 0.f;

    auto load_chunk = [&](int c) {
        const int k0 = c * 32;
        const uint32_t db = sbase + (uint32_t)(c & 1) * (FBUFW * 4);
#pragma unroll
        for (int i = 0; i < BM * 8 / THREADS; i++) {
            int u = tid + i * THREADS;
            int row = u >> 3, seg = u & 7;
            cp_async16(db + (uint32_t)(row * FSTR + seg * 4) * 4,
                       A + (size_t)(bm + row) * K + k0 + seg * 4);
        }
#pragma unroll
        for (int i = 0; i < BN * 8 / THREADS; i++) {
            int u = tid + i * THREADS;
            int row = u >> 3, seg = u & 7;
            cp_async16(db + (uint32_t)(FTILEA + row * FSTR + seg * 4) * 4,
                       B + (size_t)(bn + row) * K + k0 + seg * 4);
        }
        CP_COMMIT();
    };

    const int nchunk = K / 32;
    load_chunk(0);

    for (int c = 0; c < nchunk; c++) {
        CP_WAIT0();
        __syncthreads();
        if (c + 1 < nchunk) load_chunk(c + 1);

        const uint32_t ab = (uint32_t)(c & 1) * FBUFW;
        const uint32_t bbw = ab + FTILEA;

        auto loadf = [&](int k8, uint32_t af[2][4], uint2 bf[8]) {
            const int koff = k8 * 8 + 2 * t4;
#pragma unroll
            for (int mi = 0; mi < 2; mi++) {
                const int r0 = mrow0 + mi * 16 + g;
                uint2 u0 = *(const uint2*)&sm4[ab + r0 * FSTR + koff];
                uint2 u1 = *(const uint2*)&sm4[ab + (r0 + 8) * FSTR + koff];
                af[mi][0] = u0.x; af[mi][1] = u1.x;
                af[mi][2] = u0.y; af[mi][3] = u1.y;
            }
#pragma unroll
            for (int nt = 0; nt < 8; nt++)
                bf[nt] =
                    *(const uint2*)&sm4[bbw + (ncol0 + nt * 8 + g) * FSTR + koff];
        };
        auto mmaf = [&](uint32_t af[2][4], uint2 bf[8]) {
#pragma unroll
            for (int nt = 0; nt < 8; nt++) {
                mma_tf32(acc[0][nt], af[0], bf[nt].x, bf[nt].y);
                mma_tf32(acc[1][nt], af[1], bf[nt].x, bf[nt].y);
            }
        };

        uint32_t afA[2][4], afB[2][4];
        uint2 bfA[8], bfB[8];
        loadf(0, afA, bfA);
        loadf(1, afB, bfB);
        mmaf(afA, bfA);
        loadf(2, afA, bfA);
        mmaf(afB, bfB);
        loadf(3, afB, bfB);
        mmaf(afA, bfA);
        mmaf(afB, bfB);
    }

#pragma unroll
    for (int mi = 0; mi < 2; mi++) {
        const int r0 = bm + mrow0 + mi * 16 + g;
#pragma unroll
        for (int ni = 0; ni < 8; ni++) {
            const int col = bn + ncol0 + ni * 8 + 2 * t4;
            float b0v = 0.f, b1v = 0.f;
            if (HAS_BIAS) { b0v = bias[col]; b1v = bias[col + 1]; }
            float vals[4];
            vals[0] = acc[mi][ni][0] + b0v; vals[1] = acc[mi][ni][1] + b1v;
            vals[2] = acc[mi][ni][2] + b0v; vals[3] = acc[mi][ni][3] + b1v;
            if (ROUND_TF32) {
#pragma unroll
                for (int q = 0; q < 4; q++) vals[q] = rtf(vals[q]);
            }
            float2 v0, v1;
            v0.x = vals[0]; v0.y = vals[1];
            v1.x = vals[2]; v1.y = vals[3];
            *(float2*)(C + (size_t)r0 * N + col) = v0;
            *(float2*)(C + (size_t)(r0 + 8) * N + col) = v1;
        }
    }
}

#define GEMM1_SMEM ((128 + 128) * FSTR * 4 * 2)   // 81920
#define GEMM2_SMEM ((64 + 128) * FSTR * 4 * 2)    // 61440

// ---------------------------------------------------------------------------
// Fused shuffled-Q flash attention (tf32 mma.sync), no-rescale softmax,
// log2-domain scores, all-MUFU ex2. (R14 structure, unchanged.)
// ---------------------------------------------------------------------------
#define KSTR 72
#define VSTR 72
#define QSTR 72
#define KVBUF 9216                    // words: 64*72 + 64*72
#define VOFF 4608                     // words: 64*72
#define ATT_SMEM (2 * KVBUF * 4)      // 73728 bytes

__global__ void __launch_bounds__(256, 2) attn_kernel(
    const float* __restrict__ qkv, const int* __restrict__ perms,
    float* __restrict__ att_out) {
    extern __shared__ uint32_t sms[];
    const uint32_t sbase = smem_u32(sms);

    const int bh = blockIdx.y;
    const int b = bh / HEADS;
    const int h = bh % HEADS;
    const int q0 = blockIdx.x * 128;

    const int tid = threadIdx.x;
    const int w = tid >> 5, l = tid & 31;
    const int g = l >> 2, t4 = l & 3;
    const int qr0 = w * 16;

    const float* qkv_b = qkv + (size_t)b * SEQ * QKV_COLS;
    const int hoff = h * DHEAD;

    const int cp_row = tid >> 4;
    const int cp_seg = (tid & 15) * 4;

    auto issue_kv = [&](int t, int bsel) {
        const int kv0 = t * 64;
        const float* kb = qkv_b + (size_t)kv0 * QKV_COLS + hoff + INNER + cp_seg;
        const float* vb = kb + INNER;
        const uint32_t kd = sbase + (uint32_t)(bsel * KVBUF) * 4;
#pragma unroll
        for (int i = 0; i < 4; i++) {
            const int row = cp_row + i * 16;
            cp_async16(kd + (uint32_t)(row * KSTR + cp_seg) * 4,
                       kb + (size_t)row * QKV_COLS);
        }
#pragma unroll
        for (int i = 0; i < 4; i++) {
            const int row = cp_row + i * 16;
            cp_async16(kd + (uint32_t)(VOFF + row * VSTR + cp_seg) * 4,
                       vb + (size_t)row * QKV_COLS);
        }
        CP_COMMIT();
    };

    issue_kv(0, 0);

    // Stage Q (permuted gather, scale*log2e folded, tf32) d-interleaved.
    const float QSCALE = 0.125f * 1.44269504f;   // head-scale * log2(e)
    const int* ph = perms + (size_t)h * (SEQ * DHEAD) + q0 * DHEAD;
#pragma unroll 4
    for (int it = 0; it < 32; it++) {
        int f = it * 256 + tid;
        int p = ph[f];
        int nn = p >> 6, dd = p & 63;
        int i = f >> 6, j = f & 63;
        sms[KVBUF + i * QSTR + dplace(j)] =
            f2tf32(qkv_b[(size_t)nn * QKV_COLS + hoff + dd] * QSCALE);
    }
    __syncthreads();

    uint32_t qf[8][4];
#pragma unroll
    for (int kc = 0; kc < 8; kc++) {
        uint2 u0 = *(const uint2*)&sms[KVBUF + (qr0 + g) * QSTR + kc * 8 + 2 * t4];
        uint2 u1 =
            *(const uint2*)&sms[KVBUF + (qr0 + g + 8) * QSTR + kc * 8 + 2 * t4];
        qf[kc][0] = u0.x; qf[kc][2] = u0.y;
        qf[kc][1] = u1.x; qf[kc][3] = u1.y;
    }
    __syncthreads();   // buf1 free for tile 1

    float ls0 = 0.f, ls1 = 0.f;
    float O[8][4];
#pragma unroll
    for (int dt = 0; dt < 8; dt++)
#pragma unroll
        for (int q = 0; q < 4; q++) O[dt][q] = 0.f;

    const int srcA = (l & 28) | (t4 >> 1);
    const int srcB = srcA | 2;
    const bool lo_lane = (t4 & 1) != 0;

    for (int t = 0; t < 16; t++) {
        if (t < 15) {
            issue_kv(t + 1, (t + 1) & 1);
            CP_WAIT1();
        } else {
            CP_WAIT0();
        }
        __syncthreads();

        const uint32_t kw = (uint32_t)(t & 1) * KVBUF;
        const uint32_t vw = kw + VOFF;

        // S = Q @ K^T  (log2 domain)
        float S[8][4];
#pragma unroll
        for (int nt = 0; nt < 8; nt++)
#pragma unroll
            for (int q = 0; q < 4; q++) S[nt][q] = 0.f;
#pragma unroll
        for (int kc = 0; kc < 8; kc++) {
#pragma unroll
            for (int nt = 0; nt < 8; nt++) {
                uint2 kk = *(const uint2*)&sms[kw + (nt * 8 + g) * KSTR +
                                               kc * 8 + 2 * t4];
                mma_tf32(S[nt], qf[kc], kk.x, kk.y);
            }
        }

        // P = 2^S (single MUFU op per element); per-thread partial sums.
#pragma unroll
        for (int nt = 0; nt < 8; nt++) {
            S[nt][0] = ex2_hw(S[nt][0]);
            S[nt][1] = ex2_hw(S[nt][1]);
            S[nt][2] = ex2_hw(S[nt][2]);
            S[nt][3] = ex2_hw(S[nt][3]);
            ls0 += S[nt][0] + S[nt][1];
            ls1 += S[nt][2] + S[nt][3];
        }

        // O += P @ V  (P fragments built via warp shuffles)
#pragma unroll
        for (int kc = 0; kc < 8; kc++) {
            uint32_t p0 = f2tf32(S[kc][0]);
            uint32_t p1 = f2tf32(S[kc][1]);
            uint32_t p2 = f2tf32(S[kc][2]);
            uint32_t p3 = f2tf32(S[kc][3]);
            uint32_t v00 = __shfl_sync(0xffffffffu, p0, srcA);
            uint32_t v01 = __shfl_sync(0xffffffffu, p1, srcA);
            uint32_t v10 = __shfl_sync(0xffffffffu, p2, srcA);
            uint32_t v11 = __shfl_sync(0xffffffffu, p3, srcA);
            uint32_t w00 = __shfl_sync(0xffffffffu, p0, srcB);
            uint32_t w01 = __shfl_sync(0xffffffffu, p1, srcB);
            uint32_t w10 = __shfl_sync(0xffffffffu, p2, srcB);
            uint32_t w11 = __shfl_sync(0xffffffffu, p3, srcB);
            uint32_t a[4];
            a[0] = lo_lane ? v01 : v00;
            a[1] = lo_lane ? v11 : v10;
            a[2] = lo_lane ? w01 : w00;
            a[3] = lo_lane ? w11 : w10;
#pragma unroll
            for (int dt = 0; dt < 8; dt++) {
                uint32_t b0 = sms[vw + (kc * 8 + t4) * VSTR + dt * 8 + g];
                uint32_t b1 = sms[vw + (kc * 8 + t4 + 4) * VSTR + dt * 8 + g];
                mma_tf32(O[dt], a, b0, b1);
            }
        }
        __syncthreads();
    }

    // Final row-sum reduction across the 4 t4 lanes of each row.
    ls0 += __shfl_xor_sync(0xffffffffu, ls0, 1);
    ls0 += __shfl_xor_sync(0xffffffffu, ls0, 2);
    ls1 += __shfl_xor_sync(0xffffffffu, ls1, 1);
    ls1 += __shfl_xor_sync(0xffffffffu, ls1, 2);

    // Epilogue: normalize, tf32-round, write fp32 att with interleaved cols.
    const float inv0 = 1.0f / ls0;
    const float inv1 = 1.0f / ls1;
    const size_t r0off = ((size_t)b * SEQ + q0 + qr0 + g) * NDIM + hoff;
    const size_t r1off = r0off + (size_t)8 * NDIM;
    const int p0c = dplace(2 * t4);
    const int p1c = dplace(2 * t4 + 1);
#pragma unroll
    for (int dt = 0; dt < 8; dt++) {
        att_out[r0off + dt * 8 + p0c] = rtf(O[dt][0] * inv0);
        att_out[r0off + dt * 8 + p1c] = rtf(O[dt][1] * inv0);
        att_out[r1off + dt * 8 + p0c] = rtf(O[dt][2] * inv1);
        att_out[r1off + dt * 8 + p1c] = rtf(O[dt][3] * inv1);
    }
}

// ---------------------------------------------------------------------------
extern "C" void kernel_launch(void* const* d_in, const int* in_sizes, int n_in,
                              void* d_out, int out_size) {
    const float* x     = (const float*)d_in[0];
    const float* w_qkv = (const float*)d_in[1];
    const float* w_out = (const float*)d_in[2];
    const float* b_out = (const float*)d_in[3];
    const int*   perms = (const int*)d_in[4];
    float* out = (float*)d_out;

    float *qkv, *xt, *wt, *att, *wot;
    cudaGetSymbolAddress((void**)&qkv, g_qkv);
    cudaGetSymbolAddress((void**)&xt, g_xt);
    cudaGetSymbolAddress((void**)&wt, g_wt);
    cudaGetSymbolAddress((void**)&att, g_att);
    cudaGetSymbolAddress((void**)&wot, g_wot);

    cudaFuncSetAttribute(attn_kernel, cudaFuncAttributeMaxDynamicSharedMemorySize,
                         ATT_SMEM);
    cudaFuncSetAttribute(
        (const void*)gemm_tf32<128, 128, 256, 2, false, true>,
        cudaFuncAttributeMaxDynamicSharedMemorySize, GEMM1_SMEM);
    cudaFuncSetAttribute(
        (const void*)gemm_tf32<64, 128, 128, 3, true, false>,
        cudaFuncAttributeMaxDynamicSharedMemorySize, GEMM2_SMEM);

    // 1) one fused conversion launch: x, w_qkv (K-row ilv), w_out
    cvt_all<<<2048, 256>>>(x, w_qkv, w_out, xt, wt, wot);

    // 2) qkv = x @ w_qkv^T
    {
        dim3 grid(QKV_COLS / 128, ROWS_TOTAL / 128);  // (18, 64)
        gemm_tf32<128, 128, 256, 2, false, true><<<grid, 256, GEMM1_SMEM>>>(
            xt, wt, nullptr, qkv, ROWS_TOTAL, QKV_COLS, NDIM);
    }
    // 3) fused shuffled-Q attention -> att (fp32, col-ilv)
    {
        dim3 grid(SEQ / 128, BATCH * HEADS);  // (8, 96)
        attn_kernel<<<grid, 256, ATT_SMEM>>>(qkv, perms, att);
    }
    // 4) out = att @ w_out^T + b_out   (64x128 tiles -> 768 blocks, 3/SM:
    //    2 waves of half-size tiles instead of 2 waves of full tiles)
    {
        dim3 grid(NDIM / 128, ROWS_TOTAL / 64);  // (6, 128) = 768 blocks
        gemm_tf32<64, 128, 128, 3, true, false><<<grid, 128, GEMM2_SMEM>>>(
            att, wot, b_out, out, ROWS_TOTAL, NDIM, NDIM);
    }
}